// round 10
// baseline (speedup 1.0000x reference)
#include <cuda_runtime.h>
#include <math.h>

// Problem constants
#define BATCH 64
#define HP 64
#define HH 64
#define WW 64
#define DD 32
#define NH 2
#define DH 16
#define DFF 64
#define NPAIR (BATCH*HP)     // 4096
#define HW (HH*WW)           // 4096

// ---------------- scratch (no allocations allowed) ----------------
__device__ float g_feat[NPAIR*DD];
__device__ float g_gate[NPAIR];
__device__ float g_row [NPAIR*HH];
__device__ float g_col [NPAIR*WW];
__device__ float g_drow[NPAIR*HH];
__device__ float g_dcol[NPAIR*WW];

// ---------------- warp reduce helpers ----------------
__device__ __forceinline__ float wrsum(float v){
  #pragma unroll
  for (int o=16;o;o>>=1) v += __shfl_down_sync(0xffffffffu, v, o);
  return v;
}
__device__ __forceinline__ float wrmin(float v){
  #pragma unroll
  for (int o=16;o;o>>=1) v = fminf(v, __shfl_down_sync(0xffffffffu, v, o));
  return v;
}
__device__ __forceinline__ float wrmax(float v){
  #pragma unroll
  for (int o=16;o;o>>=1) v = fmaxf(v, __shfl_down_sync(0xffffffffu, v, o));
  return v;
}

// ================= Kernel 1: stats + in_proj =================
// one block per (b,hp) pair; 256 threads; reads 2*4096 floats via float4
__global__ __launch_bounds__(256) void stats_kernel(
    const float* __restrict__ a, const float* __restrict__ b,
    const float* __restrict__ in_w, const float* __restrict__ in_b,
    const float* __restrict__ emb)
{
  const int p   = blockIdx.x;
  const int tid = threadIdx.x;
  const float4* a4 = (const float4*)(a + (size_t)p*HW);
  const float4* b4 = (const float4*)(b + (size_t)p*HW);

  float sa=0.f, sqa=0.f, sb=0.f, sqb=0.f, sab=0.f, sqd=0.f;
  float mna=3.4e38f, mxa=-3.4e38f, mnb=3.4e38f, mxb=-3.4e38f;

  #pragma unroll
  for (int it=0; it<4; it++) {
    int i = tid + it*256;            // 1024 float4s total
    float4 av = a4[i];
    float4 bv = b4[i];
    #pragma unroll
    for (int c=0;c<4;c++){
      float x = (&av.x)[c];
      float y = (&bv.x)[c];
      sa += x;  sqa = fmaf(x,x,sqa);
      sb += y;  sqb = fmaf(y,y,sqb);
      sab = fmaf(x,y,sab);
      float d = x-y; sqd = fmaf(d,d,sqd);
      mna = fminf(mna,x); mxa = fmaxf(mxa,x);
      mnb = fminf(mnb,y); mxb = fmaxf(mxb,y);
    }
  }

  __shared__ float sm[10][8];
  __shared__ float stats[12];
  const int warp = tid>>5, lane = tid&31;
  sa=wrsum(sa); sqa=wrsum(sqa); sb=wrsum(sb); sqb=wrsum(sqb);
  sab=wrsum(sab); sqd=wrsum(sqd);
  mna=wrmin(mna); mxa=wrmax(mxa); mnb=wrmin(mnb); mxb=wrmax(mxb);
  if (lane==0){
    sm[0][warp]=sa;  sm[1][warp]=sqa; sm[2][warp]=sb; sm[3][warp]=sqb;
    sm[4][warp]=sab; sm[5][warp]=sqd;
    sm[6][warp]=mna; sm[7][warp]=mxa; sm[8][warp]=mnb; sm[9][warp]=mxb;
  }
  __syncthreads();
  // warp 0: lane r<10 reduces row r across its 8 partials
  if (warp==0 && lane<10) {
    float v = sm[lane][0];
    if (lane==6 || lane==8) { // mins
      #pragma unroll
      for (int w=1;w<8;w++) v = fminf(v, sm[lane][w]);
    } else if (lane==7 || lane==9) { // maxs
      #pragma unroll
      for (int w=1;w<8;w++) v = fmaxf(v, sm[lane][w]);
    } else {
      #pragma unroll
      for (int w=1;w<8;w++) v += sm[lane][w];
    }
    sm[lane][0] = v;
  }
  __syncthreads();
  if (tid==0){
    float t0=sm[0][0], t1=sm[1][0], t2=sm[2][0], t3=sm[3][0];
    float t4=sm[4][0], t5=sm[5][0];
    float m6=sm[6][0], m7=sm[7][0], m8=sm[8][0], m9=sm[9][0];
    const float N     = (float)HW;
    const float invN  = 1.f/N;
    const float invN1 = 1.f/(N-1.f);
    float var_a  = fmaxf((t1 - t0*t0*invN)*invN1, 0.f);
    float var_b  = fmaxf((t3 - t2*t2*invN)*invN1, 0.f);
    float sd = t0 - t2;                 // sum of diff
    float var_d  = fmaxf((t5 - sd*sd*invN)*invN1, 0.f);
    float na = sqrtf(t1), nb = sqrtf(t3);
    float cosv = t4 / (fmaxf(na,1e-8f)*fmaxf(nb,1e-8f));
    stats[0]=t0*invN;       stats[1]=sqrtf(var_a);
    stats[2]=m6;            stats[3]=m7;
    stats[4]=t2*invN;       stats[5]=sqrtf(var_b);
    stats[6]=m8;            stats[7]=m9;
    stats[8]=sd*invN;       stats[9]=sqrtf(var_d);
    stats[10]=sqrtf(t5);    stats[11]=cosv;
  }
  __syncthreads();
  if (tid < DD) {
    float acc = in_b[tid] + emb[tid];
    #pragma unroll
    for (int s=0;s<12;s++) acc = fmaf(stats[s], in_w[tid*12+s], acc);
    g_feat[p*DD + tid] = acc;
  }
}

// ================= Kernel 2: transformer + heads =================
// one block per batch; 256 threads; 64 tokens x 32 dims in smem
#define SF 33   // feat / x / ao stride
#define SQ 97   // qkv stride
#define SH 65   // ffn-hidden stride
__global__ __launch_bounds__(256) void transformer_kernel(
    const float* __restrict__ ln1_g, const float* __restrict__ ln1_b,
    const float* __restrict__ qkv_w, const float* __restrict__ qkv_b,
    const float* __restrict__ out_w, const float* __restrict__ out_b,
    const float* __restrict__ ln2_g, const float* __restrict__ ln2_b,
    const float* __restrict__ ffn_w1, const float* __restrict__ ffn_b1,
    const float* __restrict__ ffn_w2, const float* __restrict__ ffn_b2,
    const float* __restrict__ gate_w, const float* __restrict__ gate_b,
    const float* __restrict__ row_w, const float* __restrict__ row_b,
    const float* __restrict__ col_w, const float* __restrict__ col_b,
    const float* __restrict__ drow_w, const float* __restrict__ drow_b,
    const float* __restrict__ dcol_w, const float* __restrict__ dcol_b)
{
  __shared__ float feat[HP*SF];      // persistent residual stream
  __shared__ float xa[HP*SF];        // LN out, later attention out (ao)
  __shared__ float qf[HP*SQ];        // qkv buffer, later FFN hidden (stride SH)

  const int bb  = blockIdx.x;
  const int tid = threadIdx.x;
  const float* gf = g_feat + (size_t)bb*HP*DD;

  // load features (coalesced) into padded smem
  for (int i = tid; i < HP*DD; i += 256)
    feat[(i>>5)*SF + (i&31)] = gf[i];
  __syncthreads();

  // ---- LN1 ----
  if (tid < HP) {
    float m=0.f;
    #pragma unroll
    for (int d=0;d<DD;d++) m += feat[tid*SF+d];
    m *= (1.f/DD);
    float v=0.f;
    #pragma unroll
    for (int d=0;d<DD;d++){ float t=feat[tid*SF+d]-m; v = fmaf(t,t,v); }
    float r = rsqrtf(v*(1.f/DD) + 1e-5f);
    #pragma unroll
    for (int d=0;d<DD;d++)
      xa[tid*SF+d] = fmaf((feat[tid*SF+d]-m)*r, ln1_g[d], ln1_b[d]);
  }
  __syncthreads();

  // ---- QKV: 64 tokens x 96 outputs ----
  for (int o = tid; o < HP*3*DD; o += 256) {
    int j = o >> 6, t = o & 63;          // j broadcast within warp
    float acc = qkv_b[j];
    #pragma unroll
    for (int d=0;d<DD;d++) acc = fmaf(xa[t*SF+d], qkv_w[j*DD+d], acc);
    qf[t*SQ+j] = acc;
  }
  __syncthreads();

  // ---- attention (online softmax), 128 threads: (head, q-token) ----
  if (tid < NH*HP) {
    const int h = tid >> 6, q = tid & 63;
    const int qo = q*SQ + h*DH;
    float m = -3.4e38f, l = 0.f;
    float acc[DH];
    #pragma unroll
    for (int d=0;d<DH;d++) acc[d]=0.f;
    for (int k=0;k<HP;k++){
      const int ko = k*SQ + DD + h*DH;   // K block
      const int vo = k*SQ + 2*DD + h*DH; // V block
      float sc = 0.f;
      #pragma unroll
      for (int d=0;d<DH;d++) sc = fmaf(qf[qo+d], qf[ko+d], sc);
      sc *= 0.25f;                        // 1/sqrt(16)
      float mn = fmaxf(m, sc);
      float corr = __expf(m - mn);
      float p = __expf(sc - mn);
      l = fmaf(l, corr, p);
      #pragma unroll
      for (int d=0;d<DH;d++) acc[d] = fmaf(acc[d], corr, p*qf[vo+d]);
      m = mn;
    }
    float inv = 1.f/l;
    #pragma unroll
    for (int d=0;d<DH;d++) xa[q*SF + h*DH + d] = acc[d]*inv;
  }
  __syncthreads();

  // ---- out proj + residual ----
  for (int o = tid; o < HP*DD; o += 256) {
    int d = o >> 6, t = o & 63;
    float acc = out_b[d];
    #pragma unroll
    for (int e=0;e<DD;e++) acc = fmaf(xa[t*SF+e], out_w[d*DD+e], acc);
    feat[t*SF+d] += acc;
  }
  __syncthreads();

  // ---- LN2 ----
  if (tid < HP) {
    float m=0.f;
    #pragma unroll
    for (int d=0;d<DD;d++) m += feat[tid*SF+d];
    m *= (1.f/DD);
    float v=0.f;
    #pragma unroll
    for (int d=0;d<DD;d++){ float t=feat[tid*SF+d]-m; v = fmaf(t,t,v); }
    float r = rsqrtf(v*(1.f/DD) + 1e-5f);
    #pragma unroll
    for (int d=0;d<DD;d++)
      xa[tid*SF+d] = fmaf((feat[tid*SF+d]-m)*r, ln2_g[d], ln2_b[d]);
  }
  __syncthreads();

  // ---- FFN1 + exact GELU (hidden stored in qf with stride SH) ----
  for (int o = tid; o < HP*DFF; o += 256) {
    int j = o >> 6, t = o & 63;
    float acc = ffn_b1[j];
    #pragma unroll
    for (int d=0;d<DD;d++) acc = fmaf(xa[t*SF+d], ffn_w1[j*DD+d], acc);
    acc = 0.5f*acc*(1.f + erff(acc*0.70710678118654752f));
    qf[t*SH+j] = acc;
  }
  __syncthreads();

  // ---- FFN2 + residual ----
  for (int o = tid; o < HP*DD; o += 256) {
    int d = o >> 6, t = o & 63;
    float acc = ffn_b2[d];
    #pragma unroll
    for (int j=0;j<DFF;j++) acc = fmaf(qf[t*SH+j], ffn_w2[d*DFF+j], acc);
    feat[t*SF+d] += acc;
  }
  __syncthreads();

  // ---- heads: gate / row / col / drow / dcol ----
  if (tid < HP) {
    float acc = gate_b[0];
    #pragma unroll
    for (int d=0;d<DD;d++) acc = fmaf(feat[tid*SF+d], gate_w[d], acc);
    g_gate[bb*HP + tid] = acc;
  }
  // i contiguous within warp -> coalesced global stores
  for (int o = tid; o < HP*HH; o += 256) {
    int t = o >> 6, i = o & 63;
    float fr = row_b[i], fc = col_b[i], fdr = drow_b[i], fdc = dcol_b[i];
    #pragma unroll
    for (int d=0;d<DD;d++){
      float f = feat[t*SF+d];       // broadcast within warp
      fr  = fmaf(f, row_w [i*DD+d], fr);
      fc  = fmaf(f, col_w [i*DD+d], fc);
      fdr = fmaf(f, drow_w[i*DD+d], fdr);
      fdc = fmaf(f, dcol_w[i*DD+d], fdc);
    }
    int gi = (bb*HP + t)*HH + i;
    g_row[gi]=fr; g_col[gi]=fc; g_drow[gi]=fdr; g_dcol[gi]=fdc;
  }
}

// ================= Kernel 3: merge =================
// Blocks iterate pairs in REVERSED order: kernel 1 streamed p ascending, so
// the L2 (~126 MB, not flushed across launches) retains the tail of a/b.
// Reading the tail first converts those re-reads into L2 hits instead of
// LRU-chasing evicted lines.
__global__ __launch_bounds__(256) void merge_kernel(
    const float* __restrict__ a, const float* __restrict__ b,
    const float* __restrict__ dscale, float* __restrict__ out)
{
  const int p   = (NPAIR - 1) - blockIdx.x;   // reversed traversal
  const int tid = threadIdx.x;
  __shared__ float srow[HH], scol[WW], sdr[HH], sdc[WW];
  __shared__ float sgate, ssc;
  if (tid < HH) {
    int gi = p*HH + tid;
    srow[tid]=g_row[gi]; scol[tid]=g_col[gi];
    sdr[tid]=g_drow[gi]; sdc[tid]=g_dcol[gi];
  }
  if (tid==0){ sgate = g_gate[p]; ssc = *dscale; }
  __syncthreads();

  const float4* a4 = (const float4*)(a + (size_t)p*HW);
  const float4* b4 = (const float4*)(b + (size_t)p*HW);
  float4*       o4 = (float4*)(out + (size_t)p*HW);
  const float g  = sgate;
  const float sc = ssc;

  #pragma unroll
  for (int it=0; it<4; it++) {
    int i = tid + it*256;                 // 1024 float4s
    int h  = i >> 4;                      // 16 float4 per row
    int w0 = (i & 15) << 2;
    float4 av = a4[i];
    float4 bv = b4[i];
    float base = g + srow[h];
    float drh  = sdr[h]*sc;
    float4 ov;
    #pragma unroll
    for (int c=0;c<4;c++){
      float lg = base + scol[w0+c];
      float mk = 1.f/(1.f + __expf(-lg));
      float x = (&av.x)[c], y = (&bv.x)[c];
      // mk*x + (1-mk)*y + drh*dc  ==  mk*(x-y) + y + drh*dc
      (&ov.x)[c] = fmaf(mk, x - y, fmaf(drh, sdc[w0+c], y));
    }
    o4[i] = ov;
  }
}

// ================= launch =================
extern "C" void kernel_launch(void* const* d_in, const int* in_sizes, int n_in,
                              void* d_out, int out_size)
{
  const float* a        = (const float*)d_in[0];
  const float* b        = (const float*)d_in[1];
  const float* emb      = (const float*)d_in[2];
  const float* in_w     = (const float*)d_in[3];
  const float* in_b     = (const float*)d_in[4];
  const float* ln1_g    = (const float*)d_in[5];
  const float* ln1_b    = (const float*)d_in[6];
  const float* qkv_w    = (const float*)d_in[7];
  const float* qkv_b    = (const float*)d_in[8];
  const float* out_w    = (const float*)d_in[9];
  const float* out_b    = (const float*)d_in[10];
  const float* ln2_g    = (const float*)d_in[11];
  const float* ln2_b    = (const float*)d_in[12];
  const float* ffn_w1   = (const float*)d_in[13];
  const float* ffn_b1   = (const float*)d_in[14];
  const float* ffn_w2   = (const float*)d_in[15];
  const float* ffn_b2   = (const float*)d_in[16];
  const float* gate_w   = (const float*)d_in[17];
  const float* gate_b   = (const float*)d_in[18];
  const float* row_w    = (const float*)d_in[19];
  const float* row_b    = (const float*)d_in[20];
  const float* col_w    = (const float*)d_in[21];
  const float* col_b    = (const float*)d_in[22];
  const float* drow_w   = (const float*)d_in[23];
  const float* drow_b   = (const float*)d_in[24];
  const float* dcol_w   = (const float*)d_in[25];
  const float* dcol_b   = (const float*)d_in[26];
  const float* dscale   = (const float*)d_in[27];
  float* out = (float*)d_out;

  stats_kernel<<<NPAIR, 256>>>(a, b, in_w, in_b, emb);
  transformer_kernel<<<BATCH, 256>>>(
      ln1_g, ln1_b, qkv_w, qkv_b, out_w, out_b, ln2_g, ln2_b,
      ffn_w1, ffn_b1, ffn_w2, ffn_b2, gate_w, gate_b,
      row_w, row_b, col_w, col_b, drow_w, drow_b, dcol_w, dcol_b);
  merge_kernel<<<NPAIR, 256>>>(a, b, dscale, out);
}

// round 17
// speedup vs baseline: 1.1536x; 1.1536x over previous
#include <cuda_runtime.h>
#include <math.h>

// Problem constants
#define BATCH 64
#define HP 64
#define HH 64
#define WW 64
#define DD 32
#define NH 2
#define DH 16
#define DFF 64
#define NPAIR (BATCH*HP)     // 4096
#define HW (HH*WW)           // 4096

// ---------------- scratch (no allocations allowed) ----------------
__device__ float g_feat[NPAIR*DD];
__device__ float g_gate[NPAIR];
__device__ float g_row [NPAIR*HH];
__device__ float g_col [NPAIR*WW];
__device__ float g_drow[NPAIR*HH];
__device__ float g_dcol[NPAIR*WW];

// ---------------- warp reduce helpers ----------------
__device__ __forceinline__ float wrsum(float v){
  #pragma unroll
  for (int o=16;o;o>>=1) v += __shfl_down_sync(0xffffffffu, v, o);
  return v;
}
__device__ __forceinline__ float wrmin(float v){
  #pragma unroll
  for (int o=16;o;o>>=1) v = fminf(v, __shfl_down_sync(0xffffffffu, v, o));
  return v;
}
__device__ __forceinline__ float wrmax(float v){
  #pragma unroll
  for (int o=16;o;o>>=1) v = fmaxf(v, __shfl_down_sync(0xffffffffu, v, o));
  return v;
}

// ================= Kernel 1: stats + in_proj =================
__global__ __launch_bounds__(256) void stats_kernel(
    const float* __restrict__ a, const float* __restrict__ b,
    const float* __restrict__ in_w, const float* __restrict__ in_b,
    const float* __restrict__ emb)
{
  const int p   = blockIdx.x;
  const int tid = threadIdx.x;
  const float4* a4 = (const float4*)(a + (size_t)p*HW);
  const float4* b4 = (const float4*)(b + (size_t)p*HW);

  float sa=0.f, sqa=0.f, sb=0.f, sqb=0.f, sab=0.f, sqd=0.f;
  float mna=3.4e38f, mxa=-3.4e38f, mnb=3.4e38f, mxb=-3.4e38f;

  #pragma unroll
  for (int it=0; it<4; it++) {
    int i = tid + it*256;
    float4 av = a4[i];
    float4 bv = b4[i];
    #pragma unroll
    for (int c=0;c<4;c++){
      float x = (&av.x)[c];
      float y = (&bv.x)[c];
      sa += x;  sqa = fmaf(x,x,sqa);
      sb += y;  sqb = fmaf(y,y,sqb);
      sab = fmaf(x,y,sab);
      float d = x-y; sqd = fmaf(d,d,sqd);
      mna = fminf(mna,x); mxa = fmaxf(mxa,x);
      mnb = fminf(mnb,y); mxb = fmaxf(mxb,y);
    }
  }

  __shared__ float sm[10][8];
  __shared__ float stats[12];
  const int warp = tid>>5, lane = tid&31;
  sa=wrsum(sa); sqa=wrsum(sqa); sb=wrsum(sb); sqb=wrsum(sqb);
  sab=wrsum(sab); sqd=wrsum(sqd);
  mna=wrmin(mna); mxa=wrmax(mxa); mnb=wrmin(mnb); mxb=wrmax(mxb);
  if (lane==0){
    sm[0][warp]=sa;  sm[1][warp]=sqa; sm[2][warp]=sb; sm[3][warp]=sqb;
    sm[4][warp]=sab; sm[5][warp]=sqd;
    sm[6][warp]=mna; sm[7][warp]=mxa; sm[8][warp]=mnb; sm[9][warp]=mxb;
  }
  __syncthreads();
  if (warp==0 && lane<10) {
    float v = sm[lane][0];
    if (lane==6 || lane==8) {
      #pragma unroll
      for (int w=1;w<8;w++) v = fminf(v, sm[lane][w]);
    } else if (lane==7 || lane==9) {
      #pragma unroll
      for (int w=1;w<8;w++) v = fmaxf(v, sm[lane][w]);
    } else {
      #pragma unroll
      for (int w=1;w<8;w++) v += sm[lane][w];
    }
    sm[lane][0] = v;
  }
  __syncthreads();
  if (tid==0){
    float t0=sm[0][0], t1=sm[1][0], t2=sm[2][0], t3=sm[3][0];
    float t4=sm[4][0], t5=sm[5][0];
    float m6=sm[6][0], m7=sm[7][0], m8=sm[8][0], m9=sm[9][0];
    const float N     = (float)HW;
    const float invN  = 1.f/N;
    const float invN1 = 1.f/(N-1.f);
    float var_a  = fmaxf((t1 - t0*t0*invN)*invN1, 0.f);
    float var_b  = fmaxf((t3 - t2*t2*invN)*invN1, 0.f);
    float sd = t0 - t2;
    float var_d  = fmaxf((t5 - sd*sd*invN)*invN1, 0.f);
    float na = sqrtf(t1), nb = sqrtf(t3);
    float cosv = t4 / (fmaxf(na,1e-8f)*fmaxf(nb,1e-8f));
    stats[0]=t0*invN;       stats[1]=sqrtf(var_a);
    stats[2]=m6;            stats[3]=m7;
    stats[4]=t2*invN;       stats[5]=sqrtf(var_b);
    stats[6]=m8;            stats[7]=m9;
    stats[8]=sd*invN;       stats[9]=sqrtf(var_d);
    stats[10]=sqrtf(t5);    stats[11]=cosv;
  }
  __syncthreads();
  if (tid < DD) {
    float acc = in_b[tid] + emb[tid];
    #pragma unroll
    for (int s=0;s<12;s++) acc = fmaf(stats[s], in_w[tid*12+s], acc);
    g_feat[p*DD + tid] = acc;
  }
}

// ================= Kernel 2: transformer (no heads) =================
// one block per batch; 256 threads. Each thread owns token t = tid&63
// for the GEMMs; weight rows loaded via float4 (warp-uniform broadcast).
#define SF 33   // feat / x / ao stride
#define SQ 97   // qkv stride
#define SH 65   // ffn-hidden stride
__global__ __launch_bounds__(256) void transformer_kernel(
    const float* __restrict__ ln1_g, const float* __restrict__ ln1_b,
    const float* __restrict__ qkv_w, const float* __restrict__ qkv_b,
    const float* __restrict__ out_w, const float* __restrict__ out_b,
    const float* __restrict__ ln2_g, const float* __restrict__ ln2_b,
    const float* __restrict__ ffn_w1, const float* __restrict__ ffn_b1,
    const float* __restrict__ ffn_w2, const float* __restrict__ ffn_b2,
    const float* __restrict__ gate_w, const float* __restrict__ gate_b)
{
  __shared__ float feat[HP*SF];      // persistent residual stream
  __shared__ float xa[HP*SF];        // LN out / attention out
  __shared__ float qf[HP*SQ];        // qkv buffer, later FFN hidden (stride SH)

  const int bb  = blockIdx.x;
  const int tid = threadIdx.x;
  const int t    = tid & 63;         // fixed token per thread
  const int grp  = tid >> 6;         // 0..3
  float* gf = g_feat + (size_t)bb*HP*DD;

  for (int i = tid; i < HP*DD; i += 256)
    feat[(i>>5)*SF + (i&31)] = gf[i];
  __syncthreads();

  // ---- LN1 ----
  if (tid < HP) {
    float m=0.f;
    #pragma unroll
    for (int d=0;d<DD;d++) m += feat[tid*SF+d];
    m *= (1.f/DD);
    float v=0.f;
    #pragma unroll
    for (int d=0;d<DD;d++){ float x=feat[tid*SF+d]-m; v = fmaf(x,x,v); }
    float r = rsqrtf(v*(1.f/DD) + 1e-5f);
    #pragma unroll
    for (int d=0;d<DD;d++)
      xa[tid*SF+d] = fmaf((feat[tid*SF+d]-m)*r, ln1_g[d], ln1_b[d]);
  }
  __syncthreads();

  // ---- QKV: token row in regs, 24 outputs per thread (j = jj*4+grp) ----
  {
    float f[DD];
    #pragma unroll
    for (int d=0;d<DD;d++) f[d] = xa[t*SF+d];
    #pragma unroll
    for (int jj=0; jj<24; jj++) {
      int j = jj*4 + grp;               // covers 0..95 exactly once
      const float4* wr = (const float4*)(qkv_w + j*DD);
      float acc = qkv_b[j];
      #pragma unroll
      for (int q=0;q<8;q++){
        float4 w4 = wr[q];
        acc = fmaf(f[q*4+0], w4.x, acc);
        acc = fmaf(f[q*4+1], w4.y, acc);
        acc = fmaf(f[q*4+2], w4.z, acc);
        acc = fmaf(f[q*4+3], w4.w, acc);
      }
      qf[t*SQ+j] = acc;
    }
  }
  __syncthreads();

  // ---- attention (online softmax), 128 threads: (head, q-token) ----
  if (tid < NH*HP) {
    const int h = tid >> 6, q = tid & 63;
    const int qo = q*SQ + h*DH;
    float m = -3.4e38f, l = 0.f;
    float acc[DH];
    #pragma unroll
    for (int d=0;d<DH;d++) acc[d]=0.f;
    for (int k=0;k<HP;k++){
      const int ko = k*SQ + DD + h*DH;
      const int vo = k*SQ + 2*DD + h*DH;
      float sc = 0.f;
      #pragma unroll
      for (int d=0;d<DH;d++) sc = fmaf(qf[qo+d], qf[ko+d], sc);
      sc *= 0.25f;
      float mn = fmaxf(m, sc);
      float corr = __expf(m - mn);
      float p = __expf(sc - mn);
      l = fmaf(l, corr, p);
      #pragma unroll
      for (int d=0;d<DH;d++) acc[d] = fmaf(acc[d], corr, p*qf[vo+d]);
      m = mn;
    }
    float inv = 1.f/l;
    #pragma unroll
    for (int d=0;d<DH;d++) xa[q*SF + h*DH + d] = acc[d]*inv;
  }
  __syncthreads();

  // ---- out proj + residual: 8 outputs per thread (d = dd*4+grp) ----
  {
    float f[DD];
    #pragma unroll
    for (int d=0;d<DD;d++) f[d] = xa[t*SF+d];
    #pragma unroll
    for (int dd=0; dd<8; dd++){
      int d = dd*4 + grp;
      const float4* wr = (const float4*)(out_w + d*DD);
      float acc = out_b[d];
      #pragma unroll
      for (int q=0;q<8;q++){
        float4 w4 = wr[q];
        acc = fmaf(f[q*4+0], w4.x, acc);
        acc = fmaf(f[q*4+1], w4.y, acc);
        acc = fmaf(f[q*4+2], w4.z, acc);
        acc = fmaf(f[q*4+3], w4.w, acc);
      }
      feat[t*SF+d] += acc;
    }
  }
  __syncthreads();

  // ---- LN2 ----
  if (tid < HP) {
    float m=0.f;
    #pragma unroll
    for (int d=0;d<DD;d++) m += feat[tid*SF+d];
    m *= (1.f/DD);
    float v=0.f;
    #pragma unroll
    for (int d=0;d<DD;d++){ float x=feat[tid*SF+d]-m; v = fmaf(x,x,v); }
    float r = rsqrtf(v*(1.f/DD) + 1e-5f);
    #pragma unroll
    for (int d=0;d<DD;d++)
      xa[tid*SF+d] = fmaf((feat[tid*SF+d]-m)*r, ln2_g[d], ln2_b[d]);
  }
  __syncthreads();

  // ---- FFN1 + exact GELU: 16 outputs per thread ----
  {
    float f[DD];
    #pragma unroll
    for (int d=0;d<DD;d++) f[d] = xa[t*SF+d];
    #pragma unroll
    for (int jj=0; jj<16; jj++){
      int j = jj*4 + grp;
      const float4* wr = (const float4*)(ffn_w1 + j*DD);
      float acc = ffn_b1[j];
      #pragma unroll
      for (int q=0;q<8;q++){
        float4 w4 = wr[q];
        acc = fmaf(f[q*4+0], w4.x, acc);
        acc = fmaf(f[q*4+1], w4.y, acc);
        acc = fmaf(f[q*4+2], w4.z, acc);
        acc = fmaf(f[q*4+3], w4.w, acc);
      }
      acc = 0.5f*acc*(1.f + erff(acc*0.70710678118654752f));
      qf[t*SH+j] = acc;
    }
  }
  __syncthreads();

  // ---- FFN2 + residual: 8 outputs per thread, hidden from smem ----
  {
    #pragma unroll
    for (int dd=0; dd<8; dd++){
      int d = dd*4 + grp;
      const float4* wr = (const float4*)(ffn_w2 + d*DFF);
      float acc = ffn_b2[d];
      #pragma unroll
      for (int q=0;q<16;q++){
        float4 w4 = wr[q];
        acc = fmaf(qf[t*SH+q*4+0], w4.x, acc);
        acc = fmaf(qf[t*SH+q*4+1], w4.y, acc);
        acc = fmaf(qf[t*SH+q*4+2], w4.z, acc);
        acc = fmaf(qf[t*SH+q*4+3], w4.w, acc);
      }
      feat[t*SF+d] += acc;
    }
  }
  __syncthreads();

  // ---- gate + write final feat back for heads kernel ----
  if (tid < HP) {
    float acc = gate_b[0];
    #pragma unroll
    for (int d=0;d<DD;d++) acc = fmaf(feat[tid*SF+d], gate_w[d], acc);
    g_gate[bb*HP + tid] = acc;
  }
  for (int i = tid; i < HP*DD; i += 256)
    gf[i] = feat[(i>>5)*SF + (i&31)];
}

// ================= Kernel 2b: heads (row/col/drow/dcol) =================
// 1024 blocks x 256 threads; block handles 4 pairs; thread = (matrix m, col i)
// with its 32-float weight row in registers (8x LDG.128).
__global__ __launch_bounds__(256) void heads_kernel(
    const float* __restrict__ row_w,  const float* __restrict__ row_b,
    const float* __restrict__ col_w,  const float* __restrict__ col_b,
    const float* __restrict__ drow_w, const float* __restrict__ drow_b,
    const float* __restrict__ dcol_w, const float* __restrict__ dcol_b)
{
  __shared__ float ff[4][DD];
  const int p0  = blockIdx.x * 4;
  const int tid = threadIdx.x;
  if (tid < 4*DD) ff[tid>>5][tid&31] = g_feat[p0*DD + tid];
  __syncthreads();

  const int m = tid >> 6;     // 0..3 : row/col/drow/dcol (warp-uniform)
  const int i = tid & 63;
  const float* wsel = (m==0)?row_w :(m==1)?col_w :(m==2)?drow_w:dcol_w;
  const float* bsel = (m==0)?row_b :(m==1)?col_b :(m==2)?drow_b:dcol_b;
  float*       osel = (m==0)?g_row :(m==1)?g_col :(m==2)?g_drow:g_dcol;

  float w[DD];
  const float4* wr = (const float4*)(wsel + i*DD);
  #pragma unroll
  for (int q=0;q<8;q++){
    float4 v = wr[q];
    w[q*4+0]=v.x; w[q*4+1]=v.y; w[q*4+2]=v.z; w[q*4+3]=v.w;
  }
  const float bias = bsel[i];

  #pragma unroll
  for (int pp=0; pp<4; pp++){
    float acc = bias;
    #pragma unroll
    for (int d=0;d<DD;d++) acc = fmaf(ff[pp][d], w[d], acc);
    osel[(size_t)(p0+pp)*HH + i] = acc;   // i contiguous -> coalesced
  }
}

// ================= Kernel 3: merge =================
__global__ __launch_bounds__(256) void merge_kernel(
    const float* __restrict__ a, const float* __restrict__ b,
    const float* __restrict__ dscale, float* __restrict__ out)
{
  const int p   = (NPAIR - 1) - blockIdx.x;   // reversed traversal (L2 remnant)
  const int tid = threadIdx.x;
  __shared__ float srow[HH], scol[WW], sdr[HH], sdc[WW];
  __shared__ float sgate, ssc;
  if (tid < HH) {
    int gi = p*HH + tid;
    srow[tid]=g_row[gi]; scol[tid]=g_col[gi];
    sdr[tid]=g_drow[gi]; sdc[tid]=g_dcol[gi];
  }
  if (tid==0){ sgate = g_gate[p]; ssc = *dscale; }
  __syncthreads();

  const float4* a4 = (const float4*)(a + (size_t)p*HW);
  const float4* b4 = (const float4*)(b + (size_t)p*HW);
  float4*       o4 = (float4*)(out + (size_t)p*HW);
  const float g  = sgate;
  const float sc = ssc;

  #pragma unroll
  for (int it=0; it<4; it++) {
    int i = tid + it*256;
    int h  = i >> 4;
    int w0 = (i & 15) << 2;
    float4 av = a4[i];
    float4 bv = b4[i];
    float base = g + srow[h];
    float drh  = sdr[h]*sc;
    float4 ov;
    #pragma unroll
    for (int c=0;c<4;c++){
      float lg = base + scol[w0+c];
      float mk = 1.f/(1.f + __expf(-lg));
      float x = (&av.x)[c], y = (&bv.x)[c];
      (&ov.x)[c] = fmaf(mk, x - y, fmaf(drh, sdc[w0+c], y));
    }
    o4[i] = ov;
  }
}

// ================= launch =================
extern "C" void kernel_launch(void* const* d_in, const int* in_sizes, int n_in,
                              void* d_out, int out_size)
{
  const float* a        = (const float*)d_in[0];
  const float* b        = (const float*)d_in[1];
  const float* emb      = (const float*)d_in[2];
  const float* in_w     = (const float*)d_in[3];
  const float* in_b     = (const float*)d_in[4];
  const float* ln1_g    = (const float*)d_in[5];
  const float* ln1_b    = (const float*)d_in[6];
  const float* qkv_w    = (const float*)d_in[7];
  const float* qkv_b    = (const float*)d_in[8];
  const float* out_w    = (const float*)d_in[9];
  const float* out_b    = (const float*)d_in[10];
  const float* ln2_g    = (const float*)d_in[11];
  const float* ln2_b    = (const float*)d_in[12];
  const float* ffn_w1   = (const float*)d_in[13];
  const float* ffn_b1   = (const float*)d_in[14];
  const float* ffn_w2   = (const float*)d_in[15];
  const float* ffn_b2   = (const float*)d_in[16];
  const float* gate_w   = (const float*)d_in[17];
  const float* gate_b   = (const float*)d_in[18];
  const float* row_w    = (const float*)d_in[19];
  const float* row_b    = (const float*)d_in[20];
  const float* col_w    = (const float*)d_in[21];
  const float* col_b    = (const float*)d_in[22];
  const float* drow_w   = (const float*)d_in[23];
  const float* drow_b   = (const float*)d_in[24];
  const float* dcol_w   = (const float*)d_in[25];
  const float* dcol_b   = (const float*)d_in[26];
  const float* dscale   = (const float*)d_in[27];
  float* out = (float*)d_out;

  stats_kernel<<<NPAIR, 256>>>(a, b, in_w, in_b, emb);
  transformer_kernel<<<BATCH, 256>>>(
      ln1_g, ln1_b, qkv_w, qkv_b, out_w, out_b, ln2_g, ln2_b,
      ffn_w1, ffn_b1, ffn_w2, ffn_b2, gate_w, gate_b);
  heads_kernel<<<NPAIR/4, 256>>>(row_w, row_b, col_w, col_b,
                                 drow_w, drow_b, dcol_w, dcol_b);
  merge_kernel<<<NPAIR, 256>>>(a, b, dscale, out);
}